// round 17
// baseline (speedup 1.0000x reference)
// NerfMLP on GB300 (sm_103a HW, compute_103 PTX target -> legacy HMMA only).
// Round 16: head trimmed to 5 nb (33 cols needed, -5.4% MMAs) + drain-window
// scheduling at layer boundaries (last kc: m0-block then m1-block, so packs
// issue under the m1 MMA drain instead of a dead tensor window).
//  - R15 shape kept: m=2, 384 thr, 12 warps, TILE_M=384, LDS.128 weight frags.
//  - ReLU in packed half2 (bit-identical), L2 prefetch of next tile inputs,
//    float4 output fast path, bias in acc init, persistent CTAs.

#include <cuda_runtime.h>
#include <cuda_fp16.h>
#include <cstdint>

#define TILE_M 384

// SMEM layout (bytes)
#define OFF_W     0          // uint4 Wfr4[7*4*4*32] = 57344
#define OFF_BIAS  57344      // float [7*64]          = 1792
#define OFF_STEMW 59136      // float [96]            = 384
#define OFF_STEMB 59520      // float [32]            = 128
#define OFF_OUT   59648      // float [384*33]        = 50688
#define SMEM_BYTES 110336

__device__ __forceinline__ void mma_f16(float& c0, float& c1, float& c2, float& c3,
                                        uint32_t a0, uint32_t a1, uint32_t a2, uint32_t a3,
                                        uint32_t b0, uint32_t b1) {
    asm("mma.sync.aligned.m16n8k16.row.col.f32.f16.f16.f32 "
        "{%0,%1,%2,%3}, {%4,%5,%6,%7}, {%8,%9}, {%0,%1,%2,%3};"
        : "+f"(c0), "+f"(c1), "+f"(c2), "+f"(c3)
        : "r"(a0), "r"(a1), "r"(a2), "r"(a3), "r"(b0), "r"(b1));
}

__device__ __forceinline__ uint32_t pack_h2(float v0, float v1) {
    __half2 p = __floats2half2_rn(v0, v1);
    return *reinterpret_cast<uint32_t*>(&p);
}

// pack + ReLU in fp16 domain: max(rn(x),0) == rn(max(x,0))  (verified R13/R14)
__device__ __forceinline__ uint32_t pack_relu_h2(float v0, float v1) {
    __half2 p = __floats2half2_rn(v0, v1);
    __half2 z = __floats2half2_rn(0.f, 0.f);
    __half2 r = __hmax2(p, z);
    return *reinterpret_cast<uint32_t*>(&r);
}

__device__ __forceinline__ void prefetch_l2(const void* p) {
    asm volatile("prefetch.global.L2 [%0];" :: "l"(p));
}

__global__ void __launch_bounds__(384, 1)
nerf_mlp_kernel(const float* __restrict__ x,
                const float* __restrict__ noise,
                const float* __restrict__ stem_w,
                const float* __restrict__ stem_b,
                const float* __restrict__ Ws,
                const float* __restrict__ bs,
                const float* __restrict__ sigma_w,
                const float* __restrict__ sigma_b,
                const float* __restrict__ rgb_w,
                const float* __restrict__ rgb_b,
                float* __restrict__ out,
                int N, int nTiles) {
    extern __shared__ char sm[];
    uint4*  Wfr4  = (uint4*)(sm + OFF_W);
    float*  biasS = (float*)(sm + OFF_BIAS);
    float*  stemW = (float*)(sm + OFF_STEMW);
    float*  stemB = (float*)(sm + OFF_STEMB);
    float*  smOut = (float*)(sm + OFF_OUT);

    const int tid  = threadIdx.x;
    const int lane = tid & 31;
    const int wid  = tid >> 5;          // 0..11
    const int c    = lane & 3;          // quad column selector
    const int rq   = lane >> 2;         // row-in-8 / B-frag n index

    // ---- one-time weight staging: fp16 fragments, uint4 = two nb-blocks ----
    // Wfr4[((l*4+kc)*4+p)*32 + lane] = {b0(nb=2p), b1(nb=2p), b0(nb=2p+1), b1(nb=2p+1)}
    // where b0 packs W(kc*16 + 2*(lane&3) + {0,1}, n), b1 packs +8 in k,
    // n = nb*8 + (lane>>2).
    for (int fi = tid; fi < 7 * 4 * 4 * 32; fi += 384) {
        int fl = fi & 31;
        int p  = (fi >> 5) & 3;
        int kc = (fi >> 7) & 3;
        int l  = fi >> 9;
        int k0 = (fl & 3) * 2;
        uint32_t v[4];
        #pragma unroll
        for (int s = 0; s < 2; s++) {
            int n = (2 * p + s) * 8 + (fl >> 2);
            float w[4];
            #pragma unroll
            for (int q = 0; q < 4; q++) {
                int k = kc * 16 + k0 + (q >> 1) * 8 + (q & 1);
                float vv;
                if (l < 6)        vv = Ws[(l << 12) + (k << 6) + n];
                else if (n < 32)  vv = rgb_w[(k << 5) + n];
                else if (n == 32) vv = sigma_w[k];
                else              vv = 0.0f;
                w[q] = vv;
            }
            v[2 * s]     = pack_h2(w[0], w[1]);
            v[2 * s + 1] = pack_h2(w[2], w[3]);
        }
        Wfr4[fi] = make_uint4(v[0], v[1], v[2], v[3]);
    }
    for (int i = tid; i < 7 * 64; i += 384) {
        int l = i >> 6, j = i & 63;
        float v;
        if (l < 6)        v = bs[i];
        else if (j < 32)  v = rgb_b[j];
        else if (j == 32) v = sigma_b[0];
        else              v = 0.0f;
        biasS[i] = v;
    }
    if (tid < 96) stemW[tid] = stem_w[tid];
    if (tid < 32) stemB[tid] = stem_b[tid];
    __syncthreads();

    // warp owns 32 rows: thread rows = lrow0 + {0,8,16,24} (m-block*16 + {0,8})
    const int lrow0 = wid * 32 + rq;

    for (int t = blockIdx.x; t < nTiles; t += gridDim.x) {
        const long rowBase = (long)t * TILE_M + lrow0;

        uint32_t A[2][4][4];   // [m-block][kc][a0..a3], fp16x2

        // ---- first-layer input: concat(stem(x), noise) -> fp16 A frags ----
        #pragma unroll
        for (int m = 0; m < 2; m++) {
            long rl = rowBase + m * 16;
            long rh = rl + 8;
            bool vl = rl < N, vh = rh < N;
            float xl0 = 0, xl1 = 0, xl2 = 0, xh0 = 0, xh1 = 0, xh2 = 0;
            if (vl) { xl0 = x[rl * 3]; xl1 = x[rl * 3 + 1]; xl2 = x[rl * 3 + 2]; }
            if (vh) { xh0 = x[rh * 3]; xh1 = x[rh * 3 + 1]; xh2 = x[rh * 3 + 2]; }
            #pragma unroll
            for (int kc = 0; kc < 2; kc++) {          // stem cols 0..31
                #pragma unroll
                for (int h8 = 0; h8 < 2; h8++) {
                    int j = kc * 16 + 2 * c + h8 * 8;
                    float2 w0 = *(const float2*)(stemW + j);
                    float2 w1 = *(const float2*)(stemW + 32 + j);
                    float2 w2 = *(const float2*)(stemW + 64 + j);
                    float2 bb = *(const float2*)(stemB + j);
                    float sl0 = bb.x + xl0 * w0.x + xl1 * w1.x + xl2 * w2.x;
                    float sl1 = bb.y + xl0 * w0.y + xl1 * w1.y + xl2 * w2.y;
                    float sh0 = bb.x + xh0 * w0.x + xh1 * w1.x + xh2 * w2.x;
                    float sh1 = bb.y + xh0 * w0.y + xh1 * w1.y + xh2 * w2.y;
                    A[m][kc][h8 * 2]     = pack_h2(sl0, sl1);
                    A[m][kc][h8 * 2 + 1] = pack_h2(sh0, sh1);
                }
            }
            #pragma unroll
            for (int kc = 2; kc < 4; kc++) {          // noise cols 32..63
                #pragma unroll
                for (int h8 = 0; h8 < 2; h8++) {
                    int nc = (kc - 2) * 16 + 2 * c + h8 * 8;
                    float2 nl = vl ? *(const float2*)(noise + rl * 32 + nc) : make_float2(0, 0);
                    float2 nh = vh ? *(const float2*)(noise + rh * 32 + nc) : make_float2(0, 0);
                    A[m][kc][h8 * 2]     = pack_h2(nl.x, nl.y);
                    A[m][kc][h8 * 2 + 1] = pack_h2(nh.x, nh.y);
                }
            }
        }

        // ---- L2 prefetch for the NEXT tile this CTA will process ----
        {
            long nt = (long)t + gridDim.x;
            if (nt < nTiles) {
                long nb0 = nt * TILE_M + lrow0;
                #pragma unroll
                for (int m = 0; m < 2; m++) {
                    long rl = nb0 + m * 16;
                    if (rl < N) {
                        prefetch_l2(noise + rl * 32);        // 128B noise row (lo)
                        prefetch_l2(noise + (rl + 8) * 32);  // 128B noise row (hi)
                        prefetch_l2(x + rl * 3);             // x rows
                        prefetch_l2(x + (rl + 8) * 3);
                    }
                }
            }
        }

        float acc[2][8][4];

        // ---- 6 hidden layers (unrolled), drain-window boundary scheduling ----
        #pragma unroll
        for (int l = 0; l < 6; l++) {
            #pragma unroll
            for (int nb = 0; nb < 8; nb++) {
                float2 bb = *(const float2*)(biasS + l * 64 + nb * 8 + 2 * c);
                #pragma unroll
                for (int m = 0; m < 2; m++) {
                    acc[m][nb][0] = bb.x; acc[m][nb][1] = bb.y;
                    acc[m][nb][2] = bb.x; acc[m][nb][3] = bb.y;
                }
            }
            // kc 0..2: interleaved m0/m1 (max reuse of q in flight)
            #pragma unroll
            for (int kc = 0; kc < 3; kc++) {
                const uint4* pw = Wfr4 + ((l * 4 + kc) * 4) * 32 + lane;
                uint4 q[4];
                #pragma unroll
                for (int p = 0; p < 4; p++) q[p] = pw[p * 32];
                #pragma unroll
                for (int p = 0; p < 4; p++) {
                    int nb0 = 2 * p, nb1 = 2 * p + 1;
                    mma_f16(acc[0][nb0][0], acc[0][nb0][1], acc[0][nb0][2], acc[0][nb0][3],
                            A[0][kc][0], A[0][kc][1], A[0][kc][2], A[0][kc][3],
                            q[p].x, q[p].y);
                    mma_f16(acc[1][nb0][0], acc[1][nb0][1], acc[1][nb0][2], acc[1][nb0][3],
                            A[1][kc][0], A[1][kc][1], A[1][kc][2], A[1][kc][3],
                            q[p].x, q[p].y);
                    mma_f16(acc[0][nb1][0], acc[0][nb1][1], acc[0][nb1][2], acc[0][nb1][3],
                            A[0][kc][0], A[0][kc][1], A[0][kc][2], A[0][kc][3],
                            q[p].z, q[p].w);
                    mma_f16(acc[1][nb1][0], acc[1][nb1][1], acc[1][nb1][2], acc[1][nb1][3],
                            A[1][kc][0], A[1][kc][1], A[1][kc][2], A[1][kc][3],
                            q[p].z, q[p].w);
                }
            }
            // kc=3: all m0 MMAs, then all m1 MMAs -> acc[0] retires ~56 cyc early
            {
                const uint4* pw = Wfr4 + ((l * 4 + 3) * 4) * 32 + lane;
                uint4 q[4];
                #pragma unroll
                for (int p = 0; p < 4; p++) q[p] = pw[p * 32];
                #pragma unroll
                for (int p = 0; p < 4; p++) {
                    int nb0 = 2 * p, nb1 = 2 * p + 1;
                    mma_f16(acc[0][nb0][0], acc[0][nb0][1], acc[0][nb0][2], acc[0][nb0][3],
                            A[0][3][0], A[0][3][1], A[0][3][2], A[0][3][3],
                            q[p].x, q[p].y);
                    mma_f16(acc[0][nb1][0], acc[0][nb1][1], acc[0][nb1][2], acc[0][nb1][3],
                            A[0][3][0], A[0][3][1], A[0][3][2], A[0][3][3],
                            q[p].z, q[p].w);
                }
                #pragma unroll
                for (int p = 0; p < 4; p++) {
                    int nb0 = 2 * p, nb1 = 2 * p + 1;
                    mma_f16(acc[1][nb0][0], acc[1][nb0][1], acc[1][nb0][2], acc[1][nb0][3],
                            A[1][3][0], A[1][3][1], A[1][3][2], A[1][3][3],
                            q[p].x, q[p].y);
                    mma_f16(acc[1][nb1][0], acc[1][nb1][1], acc[1][nb1][2], acc[1][nb1][3],
                            A[1][3][0], A[1][3][1], A[1][3][2], A[1][3][3],
                            q[p].z, q[p].w);
                }
            }
            // pack m0 under the m1 MMA drain, then pack m1
            #pragma unroll
            for (int kc = 0; kc < 4; kc++) {
                A[0][kc][0] = pack_relu_h2(acc[0][2 * kc][0], acc[0][2 * kc][1]);
                A[0][kc][1] = pack_relu_h2(acc[0][2 * kc][2], acc[0][2 * kc][3]);
                A[0][kc][2] = pack_relu_h2(acc[0][2 * kc + 1][0], acc[0][2 * kc + 1][1]);
                A[0][kc][3] = pack_relu_h2(acc[0][2 * kc + 1][2], acc[0][2 * kc + 1][3]);
            }
            #pragma unroll
            for (int kc = 0; kc < 4; kc++) {
                A[1][kc][0] = pack_relu_h2(acc[1][2 * kc][0], acc[1][2 * kc][1]);
                A[1][kc][1] = pack_relu_h2(acc[1][2 * kc][2], acc[1][2 * kc][3]);
                A[1][kc][2] = pack_relu_h2(acc[1][2 * kc + 1][0], acc[1][2 * kc + 1][1]);
                A[1][kc][3] = pack_relu_h2(acc[1][2 * kc + 1][2], acc[1][2 * kc + 1][3]);
            }
        }

        // ---- head layer: only nb 0..4 (output needs 33 cols), -24 MMAs/warp ----
        #pragma unroll
        for (int nb = 0; nb < 5; nb++) {
            float2 bb = *(const float2*)(biasS + 6 * 64 + nb * 8 + 2 * c);
            #pragma unroll
            for (int m = 0; m < 2; m++) {
                acc[m][nb][0] = bb.x; acc[m][nb][1] = bb.y;
                acc[m][nb][2] = bb.x; acc[m][nb][3] = bb.y;
            }
        }
        #pragma unroll
        for (int kc = 0; kc < 4; kc++) {
            const uint4* pw = Wfr4 + ((6 * 4 + kc) * 4) * 32 + lane;
            uint4 q0 = pw[0 * 32];
            uint4 q1 = pw[1 * 32];
            uint4 q2 = pw[2 * 32];
            #pragma unroll
            for (int m = 0; m < 2; m++) {
                mma_f16(acc[m][0][0], acc[m][0][1], acc[m][0][2], acc[m][0][3],
                        A[m][kc][0], A[m][kc][1], A[m][kc][2], A[m][kc][3], q0.x, q0.y);
                mma_f16(acc[m][1][0], acc[m][1][1], acc[m][1][2], acc[m][1][3],
                        A[m][kc][0], A[m][kc][1], A[m][kc][2], A[m][kc][3], q0.z, q0.w);
                mma_f16(acc[m][2][0], acc[m][2][1], acc[m][2][2], acc[m][2][3],
                        A[m][kc][0], A[m][kc][1], A[m][kc][2], A[m][kc][3], q1.x, q1.y);
                mma_f16(acc[m][3][0], acc[m][3][1], acc[m][3][2], acc[m][3][3],
                        A[m][kc][0], A[m][kc][1], A[m][kc][2], A[m][kc][3], q1.z, q1.w);
                mma_f16(acc[m][4][0], acc[m][4][1], acc[m][4][2], acc[m][4][3],
                        A[m][kc][0], A[m][kc][1], A[m][kc][2], A[m][kc][3], q2.x, q2.y);
            }
        }

        // ---- head epilogue: stage rgb (cols 0..31) + sigma (col 32) per-warp ----
        #pragma unroll
        for (int m = 0; m < 2; m++) {
            int sl = lrow0 + m * 16;     // tile-local rows
            int sh = sl + 8;
            #pragma unroll
            for (int nb = 0; nb < 4; nb++) {
                int j = nb * 8 + 2 * c;
                smOut[sl * 33 + j]     = acc[m][nb][0];
                smOut[sl * 33 + j + 1] = acc[m][nb][1];
                smOut[sh * 33 + j]     = acc[m][nb][2];
                smOut[sh * 33 + j + 1] = acc[m][nb][3];
            }
            if (c == 0) {
                smOut[sl * 33 + 32] = acc[m][4][0];
                smOut[sh * 33 + 32] = acc[m][4][2];
            }
        }
        __syncwarp();
        {
            long gBase = (long)t * (TILE_M * 33) + (long)wid * (32 * 33);
            int  sBase = wid * (32 * 33);
            long rowsLeft = N - (long)t * TILE_M - wid * 32;
            if (rowsLeft >= 32) {
                // full warp-chunk: 1056 floats = 264 float4 (all bases 16B-aligned)
                const float4* s4 = (const float4*)(smOut + sBase);
                float4*       g4 = (float4*)(out + gBase);
                #pragma unroll
                for (int it = 0; it < 8; it++)
                    g4[lane + it * 32] = s4[lane + it * 32];
                if (lane < 8) g4[lane + 256] = s4[lane + 256];
            } else if (rowsLeft > 0) {
                int nfl = (int)rowsLeft * 33;
                for (int i = lane; i < nfl; i += 32)
                    out[gBase + i] = smOut[sBase + i];
            }
        }
        __syncwarp();
    }
}

extern "C" void kernel_launch(void* const* d_in, const int* in_sizes, int n_in,
                              void* d_out, int out_size) {
    const float* x       = (const float*)d_in[0];
    const float* noise   = (const float*)d_in[1];
    const float* stem_w  = (const float*)d_in[2];
    const float* stem_b  = (const float*)d_in[3];
    const float* Ws      = (const float*)d_in[4];
    const float* bs      = (const float*)d_in[5];
    const float* sigma_w = (const float*)d_in[6];
    const float* sigma_b = (const float*)d_in[7];
    const float* rgb_w   = (const float*)d_in[8];
    const float* rgb_b   = (const float*)d_in[9];
    float* out = (float*)d_out;

    int N = in_sizes[0] / 3;
    int nTiles = (N + TILE_M - 1) / TILE_M;   // ceil(2,097,152 / 384) = 5462

    cudaFuncSetAttribute(nerf_mlp_kernel,
                         cudaFuncAttributeMaxDynamicSharedMemorySize, SMEM_BYTES);

    int dev = 0, sms = 148;
    cudaGetDevice(&dev);
    cudaDeviceGetAttribute(&sms, cudaDevAttrMultiProcessorCount, dev);
    int grid = nTiles < sms ? nTiles : sms;

    nerf_mlp_kernel<<<grid, 384, SMEM_BYTES>>>(
        x, noise, stem_w, stem_b, Ws, bs, sigma_w, sigma_b, rgb_w, rgb_b,
        out, N, nTiles);
}